// round 15
// baseline (speedup 1.0000x reference)
#include <cuda_runtime.h>
#include <cuda_bf16.h>
#include <cstdint>

#define BB 16
#define PP 96
#define TT 128
#define VV 64
#define NN 16
#define DD 128

// ---------------------------------------------------------------------------
// PTX helpers
// ---------------------------------------------------------------------------
__device__ __forceinline__ uint32_t smem_to_u32(const void* p) {
    uint32_t a;
    asm("{ .reg .u64 t; cvta.to.shared.u64 t, %1; cvt.u32.u64 %0, t; }"
        : "=r"(a) : "l"(p));
    return a;
}
__device__ __forceinline__ void ldsm4(uint32_t* r, uint32_t addr) {
    asm volatile("ldmatrix.sync.aligned.m8n8.x4.shared.b16 {%0,%1,%2,%3}, [%4];"
        : "=r"(r[0]), "=r"(r[1]), "=r"(r[2]), "=r"(r[3]) : "r"(addr));
}
__device__ __forceinline__ void ldsm4t(uint32_t* r, uint32_t addr) {
    asm volatile("ldmatrix.sync.aligned.m8n8.x4.trans.shared.b16 {%0,%1,%2,%3}, [%4];"
        : "=r"(r[0]), "=r"(r[1]), "=r"(r[2]), "=r"(r[3]) : "r"(addr));
}
__device__ __forceinline__ void mma_bf16(float* d, const uint32_t* a,
                                         const uint32_t* b) {
    asm volatile(
        "mma.sync.aligned.m16n8k16.row.col.f32.bf16.bf16.f32 "
        "{%0,%1,%2,%3}, {%4,%5,%6,%7}, {%8,%9}, {%0,%1,%2,%3};"
        : "+f"(d[0]), "+f"(d[1]), "+f"(d[2]), "+f"(d[3])
        : "r"(a[0]), "r"(a[1]), "r"(a[2]), "r"(a[3]), "r"(b[0]), "r"(b[1]));
}
#define CVT_BF2(w, xhi, xlo) \
    asm("cvt.rn.bf16x2.f32 %0, %1, %2;" : "=r"(w) : "f"(xhi), "f"(xlo))
#define CP_ASYNC16(dst, src) \
    asm volatile("cp.async.ca.shared.global [%0], [%1], 16;" :: "r"(dst), "l"(src))
#define CP_COMMIT() asm volatile("cp.async.commit_group;" ::: "memory")
#define CP_WAIT1()  asm volatile("cp.async.wait_group 1;" ::: "memory")

// split fp32 pair -> hi bf16x2 word + lo residual word (low half = x0)
__device__ __forceinline__ void split2(float x0, float x1, uint32_t& h, uint32_t& l) {
    CVT_BF2(h, x1, x0);
    float f0 = __uint_as_float(h << 16);
    float f1 = __uint_as_float(h & 0xFFFF0000u);
    CVT_BF2(l, x1 - f1, x0 - f0);
}

// ---------------------------------------------------------------------------
// Scratch
// ---------------------------------------------------------------------------
__device__ uint32_t g_qmh[BB*PP*VV*64];   // qm = queries @ Gt^T, split bf16
__device__ uint32_t g_qml[BB*PP*VV*64];
__device__ uint32_t g_k2h[BB*PP*VV*64];   // k2 = keys@W2^T + b2 (pair rows)
__device__ uint32_t g_k2l[BB*PP*VV*64];
__device__ float g_Wqm[DD*DD];            // Gt[j][d] = sum_k Wkv[k][j] Wq[k][d]
__device__ float g_W2[DD*DD];             // W2[j][d] = sum_k Wout[j][k] Wkv[k][d]
__device__ float g_b2[DD];                // Wout@bkv + bout
__device__ float g_u[DD];                 // Wkv^T @ bq  (score key-side bias)
__device__ float g_zero[DD];              // zeros (qm bias)
__device__ int   g_sflag;                 // any(bq != 0)

// ---------------------------------------------------------------------------
// prep: Gt, W2, b2, u, flag
// ---------------------------------------------------------------------------
__global__ void prep(const float* __restrict__ Wq, const float* __restrict__ Wkv,
                     const float* __restrict__ Wout, const float* __restrict__ bq,
                     const float* __restrict__ bkv, const float* __restrict__ bout) {
    int w = blockIdx.y;
    int e = blockIdx.x * 256 + threadIdx.x;   // 0..16383
    int j = e >> 7, d = e & 127;
    float acc = 0.f;
    if (w == 0) {
#pragma unroll 4
        for (int k = 0; k < 128; k++)
            acc += Wkv[k * 128 + j] * Wq[k * 128 + d];
        g_Wqm[e] = acc;
        if (e < 128) {
            float s = 0.f;
            for (int k = 0; k < 128; k++) s += Wkv[k * 128 + e] * bq[k];
            g_u[e] = s;
            if (e == 0) {
                int f = 0;
                for (int k = 0; k < 128; k++) if (bq[k] != 0.f) f = 1;
                g_sflag = f;
            }
        }
    } else {
#pragma unroll 4
        for (int k = 0; k < 128; k++)
            acc += Wout[j * 128 + k] * Wkv[k * 128 + d];
        g_W2[e] = acc;
        if (e < 128) {
            float s = 0.f;
            for (int k = 0; k < 128; k++) s += Wout[e * 128 + k] * bkv[k];
            g_b2[e] = s + bout[e];
        }
    }
}

// ---------------------------------------------------------------------------
// Split-bf16 warp-tile MMA (16x32 warp tile) over 272B-stride A + resident W.
// ---------------------------------------------------------------------------
__device__ __forceinline__ void mma_tile(uint32_t a_base, int a_lo_off,
                                         uint32_t w_base, int lane,
                                         int warp_m, int warp_n, float acc[4][4]) {
    uint32_t a0 = a_base + (uint32_t)(warp_m * 16 + (lane & 15)) * 272
                + ((lane >> 4) * 16);
    int bj = warp_n * 32 + (lane & 7) + ((lane >> 4) * 8);
    uint32_t b0 = w_base + (uint32_t)bj * 272 + (((lane >> 3) & 1) * 16);
#pragma unroll
    for (int ks = 0; ks < 8; ks++) {
        uint32_t ah[4], al[4], bh[2][4], bl[2][4];
        ldsm4(ah, a0 + ks * 32);
        ldsm4(al, a0 + a_lo_off + ks * 32);
        ldsm4(bh[0], b0 + ks * 32);
        ldsm4(bh[1], b0 + 16 * 272 + ks * 32);
        ldsm4(bl[0], b0 + 34816 + ks * 32);
        ldsm4(bl[1], b0 + 34816 + 16 * 272 + ks * 32);
#pragma unroll
        for (int ni = 0; ni < 2; ni++)
#pragma unroll
            for (int s2 = 0; s2 < 2; s2++) {
                float* d = acc[2 * ni + s2];
                mma_bf16(d, ah, &bh[ni][2 * s2]);
                mma_bf16(d, ah, &bl[ni][2 * s2]);
                mma_bf16(d, al, &bh[ni][2 * s2]);
            }
    }
}

// ===========================================================================
// gemm_all: persistent (296 CTAs x 256 thr). Two partitions:
//   [0,127):   qm = queries@Gt^T            -> g_qm split bf16 (3072 tiles)
//   [127,296): y2 = keys@W2^T + b2; rows t<32 -> out fp32; t>=32 -> g_k2 split
// ===========================================================================
static constexpr int OFF_BHI  = 0;
static constexpr int OFF_BLO  = 34816;
static constexpr int OFF_A    = 69632;
static constexpr int STAGE_B  = 17408;
static constexpr int GEMM_SMEM = OFF_A + 2 * STAGE_B;   // 104448

static constexpr int NCTA = 296;
static constexpr int NQC  = 127;
static constexpr int NKC  = NCTA - NQC;   // 169
static constexpr int NQT  = BB*PP*VV/32;  // 3072
static constexpr int NKT  = BB*TT*VV/32;  // 4096

__device__ __forceinline__ void load_W256(char* smem, const float* __restrict__ W, int t) {
#pragma unroll
    for (int i = 0; i < 32; i++) {
        int e = t + 256 * i;
        int j = e >> 6, w = e & 63;
        float2 p = *(const float2*)(W + 2 * e);
        uint32_t h, l;
        split2(p.x, p.y, h, l);
        *(uint32_t*)(smem + OFF_BHI + j * 272 + w * 4) = h;
        *(uint32_t*)(smem + OFF_BLO + j * 272 + w * 4) = l;
    }
}

__global__ void __launch_bounds__(256, 2)
gemm_all(const float* __restrict__ queries, const float* __restrict__ keys,
         float* __restrict__ out) {
    extern __shared__ char smem[];
    const uint32_t sbase = smem_to_u32(smem);
    int t = threadIdx.x, lane = t & 31, wid = t >> 5;
    int warp_m = wid >> 2, warp_n = wid & 3;
    int cta = blockIdx.x;
    bool isq = cta < NQC;
    int tile  = isq ? cta : cta - NQC;
    int tstep = isq ? NQC : NKC;
    int NT    = isq ? NQT : NKT;
    const float* X    = isq ? queries : keys;
    const float* bias = isq ? g_zero : g_b2;

    load_W256(smem, isq ? g_Wqm : g_W2, t);

    int ocol0 = warp_n * 32 + 2 * (lane & 3);
    float2 bv[4];
#pragma unroll
    for (int nf = 0; nf < 4; nf++) bv[nf] = *(const float2*)(bias + ocol0 + nf * 8);

    float4 ap[4];
#pragma unroll
    for (int i = 0; i < 4; i++)
        ap[i] = ((const float4*)(X + (size_t)tile * 4096))[t + 256 * i];

    int st = 0;
    for (; tile < NT; tile += tstep) {
#pragma unroll
        for (int i = 0; i < 4; i++) {
            int e = t + 256 * i;
            int r = e >> 5, w = e & 31;
            uint32_t h0, h1, l0, l1;
            split2(ap[i].x, ap[i].y, h0, l0);
            split2(ap[i].z, ap[i].w, h1, l1);
            char* p = smem + OFF_A + st * STAGE_B + r * 272 + w * 8;
            *(uint2*)p = make_uint2(h0, h1);
            *(uint2*)(p + 8704) = make_uint2(l0, l1);
        }
        __syncthreads();

        int nxt = tile + tstep;
        if (nxt < NT) {
#pragma unroll
            for (int i = 0; i < 4; i++)
                ap[i] = ((const float4*)(X + (size_t)nxt * 4096))[t + 256 * i];
        }

        float acc[4][4];
#pragma unroll
        for (int a = 0; a < 4; a++)
#pragma unroll
            for (int c = 0; c < 4; c++) acc[a][c] = 0.f;
        mma_tile(sbase + OFF_A + st * STAGE_B, 8704, sbase + OFF_BHI,
                 lane, warp_m, warp_n, acc);

        int m0 = tile * 32;
        int orow = warp_m * 16 + (lane >> 2);
        if (isq) {
            // qm split-store
#pragma unroll
            for (int nf = 0; nf < 4; nf++) {
                int col = ocol0 + nf * 8;
                int wi = col >> 1;
                float* d = acc[nf];
                uint32_t h, l;
                size_t r0 = (size_t)(m0 + orow);
                split2(d[0], d[1], h, l);
                g_qmh[r0 * 64 + wi] = h; g_qml[r0 * 64 + wi] = l;
                split2(d[2], d[3], h, l);
                g_qmh[(r0 + 8) * 64 + wi] = h; g_qml[(r0 + 8) * 64 + wi] = l;
            }
        } else {
            int tt = (m0 >> 6) & 127;
            if (tt < 32) {
                // concat rows -> out directly (fp32)
#pragma unroll
                for (int nf = 0; nf < 4; nf++) {
                    int col = ocol0 + nf * 8;
                    float* d = acc[nf];
                    size_t r0 = (size_t)(m0 + orow);
                    *(float2*)(out + r0 * DD + col) = make_float2(d[0] + bv[nf].x, d[1] + bv[nf].y);
                    *(float2*)(out + (r0 + 8) * DD + col) = make_float2(d[2] + bv[nf].x, d[3] + bv[nf].y);
                }
            } else {
                // k2 split-store at pair-indexed rows
                int bb = m0 >> 13, v0 = m0 & 63;
                size_t prow0 = ((size_t)(bb * PP + (tt - 32))) * 64 + v0;
#pragma unroll
                for (int nf = 0; nf < 4; nf++) {
                    int col = ocol0 + nf * 8;
                    int wi = col >> 1;
                    float* d = acc[nf];
                    uint32_t h, l;
                    size_t r0 = prow0 + orow;
                    split2(d[0] + bv[nf].x, d[1] + bv[nf].y, h, l);
                    g_k2h[r0 * 64 + wi] = h; g_k2l[r0 * 64 + wi] = l;
                    split2(d[2] + bv[nf].x, d[3] + bv[nf].y, h, l);
                    g_k2h[(r0 + 8) * 64 + wi] = h; g_k2l[(r0 + 8) * 64 + wi] = l;
                }
            }
        }
        st ^= 1;
    }
}

// ===========================================================================
// attn_out: projection-free pair loop. Persistent 148 CTAs x 512 thr.
// Per pair: S = qm@y^T (y = raw keys) -> softmax gather/scatter -> W split
//           out = W @ k2  (k2 carries b2 bias; sum(W)=1)
// qm/k2 cp.async double-buffered pre-split; y register-prefetched + 1 convert.
// ===========================================================================
static constexpr int A_Y   = 0;          // y split: hi + lo(+17408) = 34816
static constexpr int A_QM  = 34816;      // 2 bufs x 34816
static constexpr int A_K2  = 104448;     // 2 bufs x 34816
static constexpr int A_S   = 174080;     // S fp32 64x272 = 17408
static constexpr int A_WS  = 191488;     // W split 64x144 hi + lo(+9216) = 18432
static constexpr int A_WF  = 209920;     // W fp32 64x272 = 17408
static constexpr int A_U   = 227328;     // u[128] fp32 (512) + s2[64] fp32 (256)
static constexpr int F_SMEM = 228096;

static constexpr int NPAIR   = BB * PP;  // 1536
static constexpr int AO_GRID = 148;

// S = qm @ y^T : 64x64x128, warp tile 16x16
__device__ __forceinline__ void mma_S(uint32_t q_base, uint32_t y_base, int lane,
                                      int warp_m, int warp_n, float acc[2][4]) {
    uint32_t a0 = q_base + (uint32_t)(warp_m * 16 + (lane & 15)) * 272
                + ((lane >> 4) * 16);
    uint32_t b0 = y_base + (uint32_t)(warp_n * 16 + (lane & 7) + ((lane >> 4) * 8)) * 272
                + (((lane >> 3) & 1) * 16);
#pragma unroll
    for (int ks = 0; ks < 8; ks++) {
        uint32_t ah[4], al[4], bh[4], bl[4];
        ldsm4(ah, a0 + ks * 32);
        ldsm4(al, a0 + 17408 + ks * 32);
        ldsm4(bh, b0 + ks * 32);
        ldsm4(bl, b0 + 17408 + ks * 32);
#pragma unroll
        for (int s2 = 0; s2 < 2; s2++) {
            float* d = acc[s2];
            mma_bf16(d, ah, &bh[2 * s2]);
            mma_bf16(d, ah, &bl[2 * s2]);
            mma_bf16(d, al, &bh[2 * s2]);
        }
    }
}

// out = W @ k2 : 64x128x64, warp tile 16x32; B via ldsm.trans from row-major k2
__device__ __forceinline__ void mma_O(uint32_t w_base, uint32_t k_base, int lane,
                                      int warp_m, int warp_n, float acc[4][4]) {
    uint32_t a0 = w_base + (uint32_t)(warp_m * 16 + (lane & 15)) * 144
                + ((lane >> 4) * 16);
    uint32_t b0 = k_base + (uint32_t)(lane & 15) * 272
                + (uint32_t)(warp_n * 32 + (lane >> 4) * 8) * 2;
#pragma unroll
    for (int ks = 0; ks < 4; ks++) {
        uint32_t ah[4], al[4], bh[2][4], bl[2][4];
        ldsm4(ah, a0 + ks * 32);
        ldsm4(al, a0 + 9216 + ks * 32);
#pragma unroll
        for (int ni = 0; ni < 2; ni++) {
            uint32_t ba = b0 + (uint32_t)ks * 16 * 272 + ni * 32;
            ldsm4t(bh[ni], ba);
            ldsm4t(bl[ni], ba + 17408);
        }
#pragma unroll
        for (int ni = 0; ni < 2; ni++)
#pragma unroll
            for (int s2 = 0; s2 < 2; s2++) {
                float* d = acc[2 * ni + s2];
                mma_bf16(d, ah, &bh[ni][2 * s2]);
                mma_bf16(d, ah, &bl[ni][2 * s2]);
                mma_bf16(d, al, &bh[ni][2 * s2]);
            }
    }
}

__global__ void __launch_bounds__(512, 1)
attn_out(const float* __restrict__ keys, const int* __restrict__ ccc,
         float* __restrict__ out) {
    extern __shared__ char smem[];
    const uint32_t sbase = smem_to_u32(smem);
    int t = threadIdx.x, lane = t & 31, wid = t >> 5;
    int warp_m = wid >> 2, warp_n = wid & 3;
    int v = t >> 3, to = t & 7;
    int sflag = g_sflag;
    float* us  = (float*)(smem + A_U);
    float* s2s = (float*)(smem + A_U + 512);

    // qm + k2 loader (split, 64 rows x 64 words each half)
    auto issueQK2 = [&](int pr, int par) {
        if (pr < NPAIR) {
            size_t base = (size_t)pr * 64 * 64;
            uint32_t dq = sbase + A_QM + par * 34816;
            uint32_t dk = sbase + A_K2 + par * 34816;
#pragma unroll
            for (int i = 0; i < 4; i++) {
                int c = t + 512 * i;            // 0..2047
                int hl = c >> 10, cd = c & 1023;
                int row = cd >> 4, off = cd & 15;
                uint32_t doff = hl * 17408 + row * 272 + off * 16;
                const uint32_t* sq = (hl ? g_qml : g_qmh) + base + (size_t)row * 64 + off * 4;
                const uint32_t* sk = (hl ? g_k2l : g_k2h) + base + (size_t)row * 64 + off * 4;
                CP_ASYNC16(dq + doff, sq);
                CP_ASYNC16(dk + doff, sk);
            }
        }
        CP_COMMIT();
    };

    // ---- init: zero WF + s2, load u; prime cp.async; prefetch first y ----
#pragma unroll
    for (int i = 0; i < 4; i++) {
        int e = t + 512 * i;
        *(float2*)(smem + A_WF + (e >> 5) * 272 + (e & 31) * 8) = make_float2(0.f, 0.f);
    }
    if (t < 128) us[t] = g_u[t];
    if (t < 64)  s2s[t] = 0.f;

    int pair = blockIdx.x;
    issueQK2(pair, 0);
    issueQK2(pair + AO_GRID, 1);

    float4 kp[4];
    {
        const float4* ks = (const float4*)keys
            + (size_t)((pair / PP) * TT + 32 + (pair % PP)) * 2048;
#pragma unroll
        for (int i = 0; i < 4; i++) kp[i] = ks[t + 512 * i];
    }
    const float scale = 0.08838834764831845f;
    int par = 0;

    for (; pair < NPAIR; pair += AO_GRID) {
        int b = pair / PP;
        CP_WAIT1();
        __syncthreads();                                    // (0) bufs ready

        // prefetch gather indices early
        const int* cv = ccc + b * (VV * NN) + v * NN;
        int i0 = cv[to], i1 = cv[to + 8];

        // ---- P0: convert raw keys -> y stage (+ optional s2 contribution) --
#pragma unroll
        for (int i = 0; i < 4; i++) {
            int e = t + 512 * i;
            int r = e >> 5, c4 = e & 31;
            uint32_t h0, h1, l0, l1;
            split2(kp[i].x, kp[i].y, h0, l0);
            split2(kp[i].z, kp[i].w, h1, l1);
            char* dst = smem + A_Y + r * 272 + c4 * 8;
            *(uint2*)dst = make_uint2(h0, h1);
            *(uint2*)(dst + 17408) = make_uint2(l0, l1);
            if (sflag) {
                float part = kp[i].x * us[4*c4] + kp[i].y * us[4*c4+1]
                           + kp[i].z * us[4*c4+2] + kp[i].w * us[4*c4+3];
                atomicAdd(&s2s[r], part);
            }
        }
        // prefetch next pair's raw keys (lands during MMAs)
        int np = pair + AO_GRID;
        if (np < NPAIR) {
            const float4* ks = (const float4*)keys
                + (size_t)((np / PP) * TT + 32 + (np % PP)) * 2048;
#pragma unroll
            for (int i = 0; i < 4; i++) kp[i] = ks[t + 512 * i];
        }
        __syncthreads();                                    // (1) y ready

        // ---- P1: S = qm @ y^T ----
        {
            float acc[2][4];
#pragma unroll
            for (int a = 0; a < 2; a++)
#pragma unroll
                for (int c = 0; c < 4; c++) acc[a][c] = 0.f;
            mma_S(sbase + A_QM + par * 34816, sbase + A_Y, lane, warp_m, warp_n, acc);
            int orow = warp_m * 16 + (lane >> 2);
#pragma unroll
            for (int s2 = 0; s2 < 2; s2++) {
                int col = warp_n * 16 + s2 * 8 + 2 * (lane & 3);
                float* d = acc[s2];
                *(float2*)(smem + A_S + orow * 272 + col * 4) = make_float2(d[0], d[1]);
                *(float2*)(smem + A_S + (orow + 8) * 272 + col * 4) = make_float2(d[2], d[3]);
            }
        }
        __syncthreads();                                    // (2) S ready

        // ---- P2: gather/softmax/scatter into dense W fp32 ----
        {
            const float* srow = (const float*)(smem + A_S + v * 272);
            float w0 = __expf((srow[i0] + s2s[i0]) * scale);
            float w1 = __expf((srow[i1] + s2s[i1]) * scale);
            float s = w0 + w1;
            s += __shfl_xor_sync(0xffffffffu, s, 1);
            s += __shfl_xor_sync(0xffffffffu, s, 2);
            s += __shfl_xor_sync(0xffffffffu, s, 4);
            float inv = 1.f / s;
            float* wrow = (float*)(smem + A_WF + v * 272);
            atomicAdd(wrow + i0, w0 * inv);
            atomicAdd(wrow + i1, w1 * inv);
        }
        __syncthreads();                                    // (3) W fp32 ready

        // ---- P3: W fp32 -> split bf16 (and self-clear WF + s2) ----
#pragma unroll
        for (int i = 0; i < 4; i++) {
            int e = t + 512 * i;
            int r = e >> 5, p2 = e & 31;
            float2* wf = (float2*)(smem + A_WF + r * 272 + p2 * 8);
            float2 pw = *wf;
            *wf = make_float2(0.f, 0.f);
            uint32_t h, l;
            split2(pw.x, pw.y, h, l);
            *(uint32_t*)(smem + A_WS + r * 144 + p2 * 4) = h;
            *(uint32_t*)(smem + A_WS + 9216 + r * 144 + p2 * 4) = l;
        }
        if (t < 64) s2s[t] = 0.f;
        __syncthreads();                                    // (4) WS ready

        // ---- P4: out = W @ k2 (bias carried in k2) ----
        {
            float acc[4][4];
#pragma unroll
            for (int a = 0; a < 4; a++)
#pragma unroll
                for (int c = 0; c < 4; c++) acc[a][c] = 0.f;
            mma_O(sbase + A_WS, sbase + A_K2 + par * 34816, lane, warp_m, warp_n, acc);
            int orow = warp_m * 16 + (lane >> 2);
            int ocol0 = warp_n * 32 + 2 * (lane & 3);
            size_t ob = (size_t)b * 8192 + (size_t)(32 + pair % PP) * 64;
#pragma unroll
            for (int nf = 0; nf < 4; nf++) {
                int col = ocol0 + nf * 8;
                float* d = acc[nf];
                *(float2*)(out + (ob + orow) * DD + col) = make_float2(d[0], d[1]);
                *(float2*)(out + (ob + orow + 8) * DD + col) = make_float2(d[2], d[3]);
            }
        }
        __syncthreads();                                    // (5) bufs free

        issueQK2(pair + 2 * AO_GRID, par);                  // refill this buf
        par ^= 1;
    }
}

// ---------------------------------------------------------------------------
extern "C" void kernel_launch(void* const* d_in, const int* in_sizes, int n_in,
                              void* d_out, int out_size) {
    const float* queries = (const float*)d_in[0];
    const float* keys    = (const float*)d_in[1];
    const int*   ccc     = (const int*)  d_in[2];
    const float* Wq      = (const float*)d_in[3];
    const float* bq      = (const float*)d_in[4];
    const float* Wkv     = (const float*)d_in[5];
    const float* bkv     = (const float*)d_in[6];
    const float* Wout    = (const float*)d_in[7];
    const float* bout    = (const float*)d_in[8];
    float* out = (float*)d_out;

    static bool attr_done = false;
    if (!attr_done) {
        cudaFuncSetAttribute(gemm_all, cudaFuncAttributeMaxDynamicSharedMemorySize, GEMM_SMEM);
        cudaFuncSetAttribute(attn_out, cudaFuncAttributeMaxDynamicSharedMemorySize, F_SMEM);
        attr_done = true;
    }

    prep<<<dim3(64, 2), 256>>>(Wq, Wkv, Wout, bq, bkv, bout);
    gemm_all<<<NCTA, 256, GEMM_SMEM>>>(queries, keys, out);
    attn_out<<<AO_GRID, 512, F_SMEM>>>(keys, ccc, out);
}